// round 1
// baseline (speedup 1.0000x reference)
#include <cuda_runtime.h>

#define BB 8
#define TTOT 100
#define NN 100000
#define MARGIN_F 0.1f
#define THRESH_F 0.5f
#define T_TILE 10
#define NSPLIT 32
#define NTHREADS 256

// Scratch (device globals; no allocation)
__device__ float4 g_retraj[BB * TTOT];
__device__ float  g_lval[BB][3];
__device__ float  g_uval[BB][3];
__device__ float4 g_pts[BB * NN];     // (x, y, z, radM or -1e30 if outside)
__device__ int    g_acc[BB * TTOT];   // per-(b,t) max, float bits (values >= 0)

__device__ __forceinline__ float fast_sqrt(float x) {
    float r;
    asm("sqrt.approx.f32 %0, %1;" : "=f"(r) : "f"(x));
    return r;
}

// Kernel 1: retrajs, per-b bounds, zero accumulators
__global__ void prep_kernel(const float* __restrict__ outputs,
                            const float* __restrict__ c2ws,
                            const float* __restrict__ ss) {
    int tid = threadIdx.x;
    for (int i = tid; i < BB * TTOT; i += blockDim.x) {
        int b = i / TTOT;
        float s = ss[b];
        const float* o = outputs + i * 3;
        const float* M = c2ws + b * 16;
        float o0 = o[0], o1 = o[1], o2 = o[2];
        float r[3];
        #pragma unroll
        for (int e = 0; e < 3; e++) {
            float a0 = M[e * 4 + 0] * s;
            float a1 = M[e * 4 + 1] * s;
            float a2 = M[e * 4 + 2] * s;
            r[e] = o0 * a0 + o1 * a1 + o2 * a2 + M[e * 4 + 3];
        }
        g_retraj[i] = make_float4(r[0], r[1], r[2], 0.0f);
        g_acc[i] = 0;
    }
    __syncthreads();
    if (tid < BB * 3) {
        int b = tid / 3, e = tid % 3;
        float thres = THRESH_F * ss[0];
        float mn = 1e30f, mx = -1e30f;
        for (int t = 0; t < TTOT; t++) {
            float4 rr = g_retraj[b * TTOT + t];
            float v = (e == 0) ? rr.x : ((e == 1) ? rr.y : rr.z);
            mn = fminf(mn, v);
            mx = fmaxf(mx, v);
        }
        g_lval[b][e] = mn - thres;
        g_uval[b][e] = mx + thres;
    }
}

// Kernel 2: per-b point table with inside mask folded into the radius
__global__ void mask_kernel(const float* __restrict__ means,
                            const float* __restrict__ scales) {
    int i = blockIdx.x * blockDim.x + threadIdx.x;
    if (i >= BB * NN) return;
    int b = i / NN;
    int n = i - b * NN;
    float mx = means[n * 3 + 0];
    float my = means[n * 3 + 1];
    float mz = means[n * 3 + 2];
    float s0 = scales[n * 3 + 0];
    float s1 = scales[n * 3 + 1];
    float s2 = scales[n * 3 + 2];
    float rad = fmaxf(s0, fmaxf(s1, s2));
    bool inside = (mx >= g_lval[b][0]) & (mx <= g_uval[b][0]) &
                  (my >= g_lval[b][1]) & (my <= g_uval[b][1]) &
                  (mz >= g_lval[b][2]) & (mz <= g_uval[b][2]);
    float w = inside ? (rad + MARGIN_F) : -1e30f;
    g_pts[i] = make_float4(mx, my, mz, w);
}

// Kernel 3: main — per (b, t-tile, n-chunk), running max of (radM - dist)
__global__ void __launch_bounds__(NTHREADS) main_kernel() {
    int b  = blockIdx.z;
    int tt = blockIdx.y;
    int s  = blockIdx.x;
    int tbase = tt * T_TILE;

    float rx[T_TILE], ry[T_TILE], rz[T_TILE], acc[T_TILE];
    #pragma unroll
    for (int j = 0; j < T_TILE; j++) {
        float4 r = g_retraj[b * TTOT + tbase + j];
        rx[j] = r.x; ry[j] = r.y; rz[j] = r.z;
        acc[j] = 0.0f;
    }

    const float4* __restrict__ pts = g_pts + (size_t)b * NN;
    const int chunk = (NN + NSPLIT - 1) / NSPLIT;
    int n0 = s * chunk;
    int n1 = n0 + chunk; if (n1 > NN) n1 = NN;

    for (int n = n0 + threadIdx.x; n < n1; n += NTHREADS) {
        float4 p = pts[n];
        #pragma unroll
        for (int j = 0; j < T_TILE; j++) {
            float dx = rx[j] - p.x;
            float dy = ry[j] - p.y;
            float dz = rz[j] - p.z;
            float d2 = dx * dx + dy * dy + dz * dz;
            float v  = p.w - fast_sqrt(d2);
            acc[j] = fmaxf(acc[j], v);
        }
    }

    // Block reduction: warp shfl max, then cross-warp via shared
    __shared__ float red[T_TILE][NTHREADS / 32];
    int lane = threadIdx.x & 31;
    int wid  = threadIdx.x >> 5;
    #pragma unroll
    for (int j = 0; j < T_TILE; j++) {
        float v = acc[j];
        #pragma unroll
        for (int o = 16; o > 0; o >>= 1)
            v = fmaxf(v, __shfl_xor_sync(0xffffffffu, v, o));
        if (lane == 0) red[j][wid] = v;
    }
    __syncthreads();
    if (threadIdx.x < T_TILE) {
        float v = red[threadIdx.x][0];
        #pragma unroll
        for (int w = 1; w < NTHREADS / 32; w++)
            v = fmaxf(v, red[threadIdx.x][w]);
        if (v > 0.0f)
            atomicMax(&g_acc[b * TTOT + tbase + threadIdx.x], __float_as_int(v));
    }
}

// Kernel 4: sum 800 accumulators, divide, write scalar
__global__ void final_kernel(float* __restrict__ out) {
    __shared__ float sh[256];
    float s = 0.0f;
    for (int i = threadIdx.x; i < BB * TTOT; i += 256)
        s += __int_as_float(g_acc[i]);
    sh[threadIdx.x] = s;
    __syncthreads();
    for (int o = 128; o > 0; o >>= 1) {
        if (threadIdx.x < o) sh[threadIdx.x] += sh[threadIdx.x + o];
        __syncthreads();
    }
    if (threadIdx.x == 0) out[0] = sh[0] / (float)(BB * TTOT);
}

extern "C" void kernel_launch(void* const* d_in, const int* in_sizes, int n_in,
                              void* d_out, int out_size) {
    const float* outputs = (const float*)d_in[0];  // (8,100,3)
    const float* c2ws    = (const float*)d_in[1];  // (8,4,4)
    const float* ss      = (const float*)d_in[2];  // (8,)
    const float* means   = (const float*)d_in[3];  // (100000,3)
    const float* scales  = (const float*)d_in[4];  // (100000,3)
    float* out = (float*)d_out;

    prep_kernel<<<1, 256>>>(outputs, c2ws, ss);
    mask_kernel<<<(BB * NN + 255) / 256, 256>>>(means, scales);
    main_kernel<<<dim3(NSPLIT, TTOT / T_TILE, BB), NTHREADS>>>();
    final_kernel<<<1, 256>>>(out);
}